// round 8
// baseline (speedup 1.0000x reference)
#include <cuda_runtime.h>
#include <cuda_fp16.h>
#include <cstdint>

// C[b] = A[b](1024x64) @ B[b](64x1024), fp32, b in [0,24).
// Single-pass fp16 mma.sync (m16n8k16, fp32 accum).
// Round 8: CTA tile 128x64, warp tile 32x32, regs capped for 3 CTAs/SM
// (occupancy was the limiter: occ 22.7%, issue 17%, nothing saturated).

#define M_DIM 1024
#define N_DIM 1024
#define K_DIM 64
#define BATCH 24
#define THREADS 256

// smem: A tile 128x64 fp16 (128B rows, SW128) + B tile transposed 64x64 fp16
#define SMEM_A 0
#define SMEM_B 16384
#define SMEM_TOTAL 24576

#define SW128(o) ((o) ^ (((o) >> 3) & 0x70))

__device__ __forceinline__ uint32_t smem_u32(const void* p) {
    uint32_t a;
    asm("{ .reg .u64 t; cvta.to.shared.u64 t, %1; cvt.u32.u64 %0, t; }"
        : "=r"(a) : "l"(p));
    return a;
}

__device__ __forceinline__ void ldsm_x4(uint32_t* r, uint32_t addr) {
    asm volatile("ldmatrix.sync.aligned.m8n8.x4.shared.b16 {%0,%1,%2,%3}, [%4];"
                 : "=r"(r[0]), "=r"(r[1]), "=r"(r[2]), "=r"(r[3])
                 : "r"(addr));
}

__device__ __forceinline__ void mma_fp16(float* c, const uint32_t* a,
                                         uint32_t b0, uint32_t b1) {
    asm volatile(
        "mma.sync.aligned.m16n8k16.row.col.f32.f16.f16.f32 "
        "{%0,%1,%2,%3}, {%4,%5,%6,%7}, {%8,%9}, {%0,%1,%2,%3};"
        : "+f"(c[0]), "+f"(c[1]), "+f"(c[2]), "+f"(c[3])
        : "r"(a[0]), "r"(a[1]), "r"(a[2]), "r"(a[3]), "r"(b0), "r"(b1));
}

__device__ __forceinline__ uint32_t packh2(float a, float b) {
    uint32_t r;
    asm("{ .reg .f16 lo, hi;\n\t"
        "  cvt.rn.f16.f32 lo, %1;\n\t"
        "  cvt.rn.f16.f32 hi, %2;\n\t"
        "  mov.b32 %0, {lo, hi}; }"
        : "=r"(r) : "f"(a), "f"(b));
    return r;
}

__global__ void __launch_bounds__(THREADS, 3)
bmm_fp16_kernel(const float* __restrict__ A,
                const float* __restrict__ B,
                float* __restrict__ C) {
    extern __shared__ __align__(1024) char smem[];
    const uint32_t smem_base = smem_u32(smem);
    const int tid = threadIdx.x;
    const int wid = tid >> 5;
    const int lid = tid & 31;

    const int bz   = blockIdx.z;
    const int row0 = blockIdx.y * 128;
    const int col0 = blockIdx.x * 64;

    const float* __restrict__ Ab = A + (size_t)bz * M_DIM * K_DIM;
    const float* __restrict__ Bb = B + (size_t)bz * K_DIM * N_DIM;
    float*       __restrict__ Cb = C + (size_t)bz * M_DIM * N_DIM;

    // ---- A tile: [128 m][64 k] fp32 -> fp16 smem (row-major 128B rows, SW128) ----
#pragma unroll
    for (int i = 0; i < 8; i++) {
        const int f = tid + i * THREADS;    // float4 id
        const int r = f >> 4;
        const int q = f & 15;               // k quad
        float4 v = *reinterpret_cast<const float4*>(
            &Ab[(size_t)(row0 + r) * K_DIM + q * 4]);
        uint2 h = make_uint2(packh2(v.x, v.y), packh2(v.z, v.w));
        const uint32_t off = SW128((uint32_t)(r * 128 + q * 8));
        *reinterpret_cast<uint2*>(smem + SMEM_A + off) = h;
    }

    // ---- B tile: global [64 k][64 n] -> smem BT[n][k] fp16 (SW128) ----
    // Thread owns column n = tid&63 for k-range (tid>>6)*16 .. +15 (two k8 groups).
    {
        const int n  = tid & 63;
        const int kh = (tid >> 6) * 16;
        const float* bcol = Bb + col0 + n;
#pragma unroll
        for (int k8 = 0; k8 < 2; k8++) {
            float v[8];
#pragma unroll
            for (int j = 0; j < 8; j++)
                v[j] = bcol[(size_t)(kh + k8 * 8 + j) * N_DIM];
            uint4 h;
            h.x = packh2(v[0], v[1]); h.y = packh2(v[2], v[3]);
            h.z = packh2(v[4], v[5]); h.w = packh2(v[6], v[7]);
            const uint32_t off = SW128((uint32_t)(n * 128 + (kh + k8 * 8) * 2));
            *reinterpret_cast<uint4*>(smem + SMEM_B + off) = h;
        }
    }

    __syncthreads();

    // ---- warp tiling: warp_m = wid&3 (32 rows), warp_n = wid>>2 (32 cols) ----
    const int warp_m = wid & 3;
    const int warp_n = wid >> 2;
    const int g = lid >> 3;
    const int r8 = lid & 7;
    const int a_row_l = warp_m * 32 + (g & 1) * 8 + r8;
    const int a_kb_l  = (g >> 1) * 16;
    const int b_row_l = warp_n * 32 + (g >> 1) * 8 + r8;
    const int b_kb_l  = (g & 1) * 16;

    float acc[2][4][4];
#pragma unroll
    for (int mi = 0; mi < 2; mi++)
#pragma unroll
        for (int ni = 0; ni < 4; ni++)
#pragma unroll
            for (int j = 0; j < 4; j++) acc[mi][ni][j] = 0.0f;

#pragma unroll
    for (int ks = 0; ks < 4; ks++) {
        uint32_t af[2][4];
        ldsm_x4(af[0], smem_base + SMEM_A +
                       SW128((uint32_t)(a_row_l * 128 + ks * 32 + a_kb_l)));
        ldsm_x4(af[1], smem_base + SMEM_A +
                       SW128((uint32_t)((a_row_l + 16) * 128 + ks * 32 + a_kb_l)));
        uint32_t bf[4][2];
#pragma unroll
        for (int nq = 0; nq < 2; nq++) {
            uint32_t rr[4];
            ldsm_x4(rr, smem_base + SMEM_B +
                        SW128((uint32_t)((b_row_l + nq * 16) * 128 + ks * 32 + b_kb_l)));
            bf[nq * 2 + 0][0] = rr[0]; bf[nq * 2 + 0][1] = rr[1];
            bf[nq * 2 + 1][0] = rr[2]; bf[nq * 2 + 1][1] = rr[3];
        }
#pragma unroll
        for (int mi = 0; mi < 2; mi++)
#pragma unroll
            for (int ni = 0; ni < 4; ni++)
                mma_fp16(acc[mi][ni], af[mi], bf[ni][0], bf[ni][1]);
    }

    // ---- epilogue: direct float2 stores ----
    const int tq = lid & 3;
    const int tr = lid >> 2;
#pragma unroll
    for (int mi = 0; mi < 2; mi++) {
        const int rbase = row0 + warp_m * 32 + mi * 16 + tr;
        float* c0 = &Cb[(size_t)rbase * N_DIM + col0 + warp_n * 32 + tq * 2];
        float* c1 = c0 + 8 * N_DIM;
#pragma unroll
        for (int ni = 0; ni < 4; ni++) {
            *reinterpret_cast<float2*>(c0 + ni * 8) =
                make_float2(acc[mi][ni][0], acc[mi][ni][1]);
            *reinterpret_cast<float2*>(c1 + ni * 8) =
                make_float2(acc[mi][ni][2], acc[mi][ni][3]);
        }
    }
}

extern "C" void kernel_launch(void* const* d_in, const int* in_sizes, int n_in,
                              void* d_out, int out_size) {
    const float* A = (const float*)d_in[0];   // [2,12,1024,64]
    const float* B = (const float*)d_in[1];   // [2,12,64,1024]
    float* C = (float*)d_out;                 // [2,12,1024,1024]

    cudaFuncSetAttribute(bmm_fp16_kernel,
                         cudaFuncAttributeMaxDynamicSharedMemorySize, SMEM_TOTAL);
    dim3 grid(N_DIM / 64, M_DIM / 128, BATCH);  // (16, 8, 24)
    bmm_fp16_kernel<<<grid, THREADS, SMEM_TOTAL>>>(A, B, C);
}

// round 9
// speedup vs baseline: 1.1179x; 1.1179x over previous
#include <cuda_runtime.h>
#include <cuda_fp16.h>
#include <cstdint>

// C[b] = A[b](1024x64) @ B[b](64x1024), fp32, b in [0,24).
// fp16 mma.sync m16n8k16 (fp32 accum), CTA 128x128, warp 32x64, K=64 resident.
// Round 9: B columns permuted in smem so each thread's C values are globally
// contiguous -> epilogue is pure STG.128 (halves epilogue L1 wavefronts).

#define M_DIM 1024
#define N_DIM 1024
#define K_DIM 64
#define BATCH 24
#define THREADS 256

#define SMEM_A 0
#define SMEM_B 16384
#define SMEM_TOTAL 32768

#define SW128(o) ((o) ^ (((o) >> 3) & 0x70))

__device__ __forceinline__ uint32_t smem_u32(const void* p) {
    uint32_t a;
    asm("{ .reg .u64 t; cvta.to.shared.u64 t, %1; cvt.u32.u64 %0, t; }"
        : "=r"(a) : "l"(p));
    return a;
}

__device__ __forceinline__ void ldsm_x4(uint32_t* r, uint32_t addr) {
    asm volatile("ldmatrix.sync.aligned.m8n8.x4.shared.b16 {%0,%1,%2,%3}, [%4];"
                 : "=r"(r[0]), "=r"(r[1]), "=r"(r[2]), "=r"(r[3])
                 : "r"(addr));
}

__device__ __forceinline__ void mma_fp16(float* c, const uint32_t* a,
                                         uint32_t b0, uint32_t b1) {
    asm volatile(
        "mma.sync.aligned.m16n8k16.row.col.f32.f16.f16.f32 "
        "{%0,%1,%2,%3}, {%4,%5,%6,%7}, {%8,%9}, {%0,%1,%2,%3};"
        : "+f"(c[0]), "+f"(c[1]), "+f"(c[2]), "+f"(c[3])
        : "r"(a[0]), "r"(a[1]), "r"(a[2]), "r"(a[3]), "r"(b0), "r"(b1));
}

__device__ __forceinline__ uint32_t packh2(float a, float b) {
    uint32_t r;
    asm("{ .reg .f16 lo, hi;\n\t"
        "  cvt.rn.f16.f32 lo, %1;\n\t"
        "  cvt.rn.f16.f32 hi, %2;\n\t"
        "  mov.b32 %0, {lo, hi}; }"
        : "=r"(r) : "f"(a), "f"(b));
    return r;
}

// Column permutation within a 64-col warp block.
// Fragment position p = ni*8 + tq*2 + e holds global col
//   g = (ni>>1)*16 + tq*4 + (ni&1)*2 + e.
// Inverse (used at load): given g, smem row p:
//   ni = ((g>>4)&3)*2 | ((g>>1)&1),  tq = (g>>2)&3,  e = g&1.
__device__ __forceinline__ int bperm(int gb) {
    const int ni = (((gb >> 4) & 3) << 1) | ((gb >> 1) & 1);
    const int tq = (gb >> 2) & 3;
    return ni * 8 + tq * 2 + (gb & 1);
}

__global__ void __launch_bounds__(THREADS, 2)
bmm_fp16_kernel(const float* __restrict__ A,
                const float* __restrict__ B,
                float* __restrict__ C) {
    extern __shared__ __align__(1024) char smem[];
    const uint32_t smem_base = smem_u32(smem);
    const int tid = threadIdx.x;
    const int wid = tid >> 5;
    const int lid = tid & 31;

    const int bz   = blockIdx.z;
    const int row0 = blockIdx.y * 128;
    const int col0 = blockIdx.x * 128;

    const float* __restrict__ Ab = A + (size_t)bz * M_DIM * K_DIM;
    const float* __restrict__ Bb = B + (size_t)bz * K_DIM * N_DIM;
    float*       __restrict__ Cb = C + (size_t)bz * M_DIM * N_DIM;

    // ---- A tile: [128 m][64 k] fp32 -> fp16 smem (row-major 128B rows, SW128) ----
#pragma unroll
    for (int i = 0; i < 8; i++) {
        const int f = tid + i * THREADS;    // float4 id
        const int r = f >> 4;
        const int q = f & 15;               // k quad
        float4 v = *reinterpret_cast<const float4*>(
            &Ab[(size_t)(row0 + r) * K_DIM + q * 4]);
        uint2 h = make_uint2(packh2(v.x, v.y), packh2(v.z, v.w));
        const uint32_t off = SW128((uint32_t)(r * 128 + q * 8));
        *reinterpret_cast<uint2*>(smem + SMEM_A + off) = h;
    }

    // ---- B tile: global [64 k][128 n] -> smem BT[perm(n)][k] fp16 (SW128) ----
    {
        const int n  = tid & 127;           // global column within CTA block
        const int kh = (tid >> 7) * 32;
        const int srow = (n & 64) + bperm(n & 63);   // permuted smem row
        const float* bcol = Bb + col0 + n;
#pragma unroll
        for (int k8 = 0; k8 < 4; k8++) {
            float v[8];
#pragma unroll
            for (int j = 0; j < 8; j++)
                v[j] = bcol[(size_t)(kh + k8 * 8 + j) * N_DIM];
            uint4 h;
            h.x = packh2(v[0], v[1]); h.y = packh2(v[2], v[3]);
            h.z = packh2(v[4], v[5]); h.w = packh2(v[6], v[7]);
            const uint32_t off = SW128((uint32_t)(srow * 128 + (kh + k8 * 8) * 2));
            *reinterpret_cast<uint4*>(smem + SMEM_B + off) = h;
        }
    }

    __syncthreads();

    // ---- warp tiling: warp_m = wid&3 (32 rows), warp_n = wid>>2 (64 cols) ----
    const int warp_m = wid & 3;
    const int warp_n = wid >> 2;
    const int g = lid >> 3;
    const int r8 = lid & 7;
    const int a_row_l = warp_m * 32 + (g & 1) * 8 + r8;
    const int a_kb_l  = (g >> 1) * 16;
    const int b_row_l = warp_n * 64 + (g >> 1) * 8 + r8;
    const int b_kb_l  = (g & 1) * 16;

    float acc[2][8][4];
#pragma unroll
    for (int mi = 0; mi < 2; mi++)
#pragma unroll
        for (int ni = 0; ni < 8; ni++)
#pragma unroll
            for (int j = 0; j < 4; j++) acc[mi][ni][j] = 0.0f;

#pragma unroll
    for (int ks = 0; ks < 4; ks++) {
        uint32_t af[2][4];
        ldsm_x4(af[0], smem_base + SMEM_A +
                       SW128((uint32_t)(a_row_l * 128 + ks * 32 + a_kb_l)));
        ldsm_x4(af[1], smem_base + SMEM_A +
                       SW128((uint32_t)((a_row_l + 16) * 128 + ks * 32 + a_kb_l)));
        uint32_t bf[8][2];
#pragma unroll
        for (int nq = 0; nq < 4; nq++) {
            uint32_t rr[4];
            ldsm_x4(rr, smem_base + SMEM_B +
                        SW128((uint32_t)((b_row_l + nq * 16) * 128 + ks * 32 + b_kb_l)));
            bf[nq * 2 + 0][0] = rr[0]; bf[nq * 2 + 0][1] = rr[1];
            bf[nq * 2 + 1][0] = rr[2]; bf[nq * 2 + 1][1] = rr[3];
        }
#pragma unroll
        for (int mi = 0; mi < 2; mi++)
#pragma unroll
            for (int ni = 0; ni < 8; ni++)
                mma_fp16(acc[mi][ni], af[mi], bf[ni][0], bf[ni][1]);
    }

    // ---- epilogue: permutation makes each thread's row data contiguous ----
    // Thread (tr, tq): row tr holds global cols c*16 + tq*4 .. +3 for c=0..3
    // from acc[mi][2c][0,1] ++ acc[mi][2c+1][0,1]; row tr+8 from regs [2,3].
    const int tq = lid & 3;
    const int tr = lid >> 2;
#pragma unroll
    for (int mi = 0; mi < 2; mi++) {
        const int rbase = row0 + warp_m * 32 + mi * 16 + tr;
        float* c0 = &Cb[(size_t)rbase * N_DIM + col0 + warp_n * 64 + tq * 4];
        float* c1 = c0 + 8 * N_DIM;
#pragma unroll
        for (int c = 0; c < 4; c++) {
            float4 v0 = make_float4(acc[mi][2 * c][0], acc[mi][2 * c][1],
                                    acc[mi][2 * c + 1][0], acc[mi][2 * c + 1][1]);
            float4 v1 = make_float4(acc[mi][2 * c][2], acc[mi][2 * c][3],
                                    acc[mi][2 * c + 1][2], acc[mi][2 * c + 1][3]);
            *reinterpret_cast<float4*>(c0 + c * 16) = v0;
            *reinterpret_cast<float4*>(c1 + c * 16) = v1;
        }
    }
}

extern "C" void kernel_launch(void* const* d_in, const int* in_sizes, int n_in,
                              void* d_out, int out_size) {
    const float* A = (const float*)d_in[0];   // [2,12,1024,64]
    const float* B = (const float*)d_in[1];   // [2,12,64,1024]
    float* C = (float*)d_out;                 // [2,12,1024,1024]

    cudaFuncSetAttribute(bmm_fp16_kernel,
                         cudaFuncAttributeMaxDynamicSharedMemorySize, SMEM_TOTAL);
    dim3 grid(N_DIM / 128, M_DIM / 128, BATCH);  // (8, 8, 24)
    bmm_fp16_kernel<<<grid, THREADS, SMEM_TOTAL>>>(A, B, C);
}